// round 6
// baseline (speedup 1.0000x reference)
#include <cuda_runtime.h>
#include <cuda_fp16.h>
#include <math.h>

#ifndef M_PI
#define M_PI 3.14159265358979323846
#endif

#define NBETA   12
#define NALPHA  12
#define DIM     36
#define NCH     128
#define NTYPE   10
#define WSIZE   (3 * NTYPE * NCH * 6)   // 23040

// ---- hard-coded 12-point Gauss-Legendre nodes/weights ----
__constant__ double c_glx[NBETA] = {
    -0.9815606342467192, -0.9041172563704749, -0.7699026741943047,
    -0.5873179542866175, -0.3678314989981802, -0.1252334085114689,
     0.1252334085114689,  0.3678314989981802,  0.5873179542866175,
     0.7699026741943047,  0.9041172563704749,  0.9815606342467192
};
__constant__ double c_glw[NBETA] = {
    0.0471753363865118, 0.1069393259953184, 0.1600783285433462,
    0.2031674267230659, 0.2334925365383548, 0.2491470458134028,
    0.2491470458134028, 0.2334925365383548, 0.2031674267230659,
    0.1600783285433462, 0.1069393259953184, 0.0471753363865118
};

// Packed factored tables (single strided load in main kernel):
//   [0,432)    Pk   [432,864) Pwk   [864,1008) ang (a*12+mi, [11] pad)
#define TBL_PK   0
#define TBL_PW   432
#define TBL_ANG  864
#define TBL_SIZE 1008
__device__ float g_tbl[TBL_SIZE];

__global__ void init_tables_kernel() {
    int t = threadIdx.x;
    if (t < NBETA) {
        double x = c_glx[t];
        double w = c_glw[t];
        double P[6][6];
        double s = sqrt(fmax(1.0 - x * x, 0.0));
        P[0][0] = sqrt(1.0 / (4.0 * M_PI));
        for (int m = 1; m <= 5; ++m)
            P[m][m] = sqrt((2.0 * m + 1.0) / (2.0 * m)) * s * P[m - 1][m - 1];
        for (int m = 0; m < 5; ++m)
            P[m + 1][m] = sqrt(2.0 * m + 3.0) * x * P[m][m];
        for (int m = 0; m <= 5; ++m)
            for (int l = m + 2; l <= 5; ++l) {
                double aa = sqrt((4.0 * l * l - 1.0) / ((double)l * l - (double)m * m));
                double bb = sqrt((((l - 1.0) * (l - 1.0)) - (double)m * m) /
                                 (4.0 * (l - 1.0) * (l - 1.0) - 1.0));
                P[l][m] = aa * (x * P[l - 1][m] - bb * P[l - 2][m]);
            }
        double wfac = w * (2.0 * M_PI / (double)NALPHA);
        for (int k = 0; k < DIM; ++k) {
            int l = 0;
            while (k >= (l + 1) * (l + 1)) ++l;
            int m = k - l * l - l;
            double v = P[l][m < 0 ? -m : m];
            g_tbl[TBL_PK + t * DIM + k] = (float)v;
            g_tbl[TBL_PW + t * DIM + k] = (float)(v * wfac);
        }
    } else if (t < NBETA + NALPHA) {
        int a = t - NBETA;
        double alpha = a * (2.0 * M_PI / (double)NALPHA);
        double s2 = sqrt(2.0);
        for (int mi = 0; mi < 12; ++mi) g_tbl[TBL_ANG + a * 12 + mi] = 0.0f;
        g_tbl[TBL_ANG + a * 12 + 5] = 1.0f;
        for (int m = 1; m <= 5; ++m) {
            g_tbl[TBL_ANG + a * 12 + 5 + m] = (float)(s2 * cos(m * alpha));
            g_tbl[TBL_ANG + a * 12 + 5 - m] = (float)(s2 * sin(m * alpha));
        }
    }
}

// ---------------------------------------------------------------------------
// Main kernel: block = 1 atom, thread = 1 channel.
// fg cached in fp16 smem (f exact in pass A; only pass B multiplier rounded).
// Weights computed AFTER pass B; c0 reloaded from feat for the final combine
// to shrink the live register set (target 4 blocks/SM = 16 warps).
// ---------------------------------------------------------------------------
__global__ __launch_bounds__(NCH, 4) void tp_main_kernel(
    const float* __restrict__ feat,    // [n, 128, 36]
    const float* __restrict__ atype,   // [n, 10]
    const float* __restrict__ W,       // [3, 10, 128, 6]
    float* __restrict__ out)           // [n, 128, 36]
{
    constexpr int KM[DIM] = {5,
                             4,5,6,
                             3,4,5,6,7,
                             2,3,4,5,6,7,8,
                             1,2,3,4,5,6,7,8,9,
                             0,1,2,3,4,5,6,7,8,9,10};
    constexpr int KL[DIM] = {0,
                             1,1,1,
                             2,2,2,2,2,
                             3,3,3,3,3,3,3,
                             4,4,4,4,4,4,4,4,4,
                             5,5,5,5,5,5,5,5,5,5,5};

    extern __shared__ float sm[];
    float*  sPk  = sm + TBL_PK;    // 432
    float*  sPw  = sm + TBL_PW;    // 432
    float*  sAng = sm + TBL_ANG;   // 144
    float*  sAt  = sm + TBL_SIZE;  // 16 (pad to 1024 floats)
    __half* sFg  = reinterpret_cast<__half*>(sm + 1024);  // 144*128 fp16

    const int tid = threadIdx.x;
    const int n   = blockIdx.x;

    for (int i = tid; i < TBL_SIZE; i += NCH) sm[i] = g_tbl[i];
    if (tid < NTYPE) sAt[tid] = atype[(size_t)n * NTYPE + tid];
    __syncthreads();

    const size_t base = ((size_t)n * NCH + tid) * DIM;

    // ---- load coefficients ----
    float c0[DIM];
    {
        const float4* fp = reinterpret_cast<const float4*>(feat + base);
        #pragma unroll
        for (int q = 0; q < 9; ++q) {
            float4 v = fp[q];
            c0[4*q+0] = v.x; c0[4*q+1] = v.y; c0[4*q+2] = v.z; c0[4*q+3] = v.w;
        }
    }

    // =================== pass A: fg = Y c0 ; p1 = Yw^T (fg*fg) ===============
    float p1[DIM];
    #pragma unroll
    for (int k = 0; k < DIM; ++k) p1[k] = 0.f;

    #pragma unroll 1
    for (int b = 0; b < NBETA; ++b) {
        float t[11];
        #pragma unroll
        for (int mi = 0; mi < 11; ++mi) t[mi] = 0.f;
        #pragma unroll
        for (int k = 0; k < DIM; ++k)
            t[KM[k]] = fmaf(sPk[b * DIM + k], c0[k], t[KM[k]]);

        float u[11];
        #pragma unroll
        for (int mi = 0; mi < 11; ++mi) u[mi] = 0.f;
        #pragma unroll
        for (int a = 0; a < NALPHA; ++a) {
            const float* an = sAng + a * 12;
            float f = t[0] * an[0];
            #pragma unroll
            for (int mi = 1; mi < 11; ++mi) f = fmaf(t[mi], an[mi], f);
            sFg[(b * NALPHA + a) * NCH + tid] = __float2half(f);
            float g = f * f;                 // exact f here; fp16 only in pass B
            #pragma unroll
            for (int mi = 0; mi < 11; ++mi) u[mi] = fmaf(g, an[mi], u[mi]);
        }
        #pragma unroll
        for (int k = 0; k < DIM; ++k)
            p1[k] = fmaf(sPw[b * DIM + k], u[KM[k]], p1[k]);
    }
    // c0 dead here (reloaded later) — shrinks pass-B live set

    // ============ pass B: p2 = Yw^T ((Y p1) * fg) ============================
    float p2[DIM];
    #pragma unroll
    for (int k = 0; k < DIM; ++k) p2[k] = 0.f;

    #pragma unroll 1
    for (int b = 0; b < NBETA; ++b) {
        float t[11];
        #pragma unroll
        for (int mi = 0; mi < 11; ++mi) t[mi] = 0.f;
        #pragma unroll
        for (int k = 0; k < DIM; ++k)
            t[KM[k]] = fmaf(sPk[b * DIM + k], p1[k], t[KM[k]]);

        float u[11];
        #pragma unroll
        for (int mi = 0; mi < 11; ++mi) u[mi] = 0.f;
        #pragma unroll
        for (int a = 0; a < NALPHA; ++a) {
            const float* an = sAng + a * 12;
            float f = t[0] * an[0];
            #pragma unroll
            for (int mi = 1; mi < 11; ++mi) f = fmaf(t[mi], an[mi], f);
            float g = f * __half2float(sFg[(b * NALPHA + a) * NCH + tid]);
            #pragma unroll
            for (int mi = 0; mi < 11; ++mi) u[mi] = fmaf(g, an[mi], u[mi]);
        }
        #pragma unroll
        for (int k = 0; k < DIM; ++k)
            p2[k] = fmaf(sPw[b * DIM + k], u[KM[k]], p2[k]);
    }

    // ---- weights (deferred to keep them out of the hot passes) ----
    float w0[6], w1[6], w2[6];
    #pragma unroll
    for (int l = 0; l < 6; ++l) { w0[l] = 0.f; w1[l] = 0.f; w2[l] = 0.f; }
    #pragma unroll 1
    for (int e = 0; e < NTYPE; ++e) {
        float a = sAt[e];
        const float* Wp = W + ((size_t)e * NCH + tid) * 6;
        #pragma unroll
        for (int l = 0; l < 6; ++l) {
            w0[l] = fmaf(a, Wp[l],                       w0[l]);
            w1[l] = fmaf(a, Wp[NTYPE * NCH * 6 + l],     w1[l]);
            w2[l] = fmaf(a, Wp[2 * NTYPE * NCH * 6 + l], w2[l]);
        }
    }

    // ---- final combine: reload c0 chunk-wise (L2 hit) + vectorized store ----
    const float4* fp = reinterpret_cast<const float4*>(feat + base);
    float* op = out + base;
    #pragma unroll
    for (int q = 0; q < 9; ++q) {
        float4 cv = fp[q];
        float4 v;
        v.x = fmaf(w0[KL[4*q+0]], cv.x, fmaf(w1[KL[4*q+0]], p1[4*q+0], w2[KL[4*q+0]] * p2[4*q+0]));
        v.y = fmaf(w0[KL[4*q+1]], cv.y, fmaf(w1[KL[4*q+1]], p1[4*q+1], w2[KL[4*q+1]] * p2[4*q+1]));
        v.z = fmaf(w0[KL[4*q+2]], cv.z, fmaf(w1[KL[4*q+2]], p1[4*q+2], w2[KL[4*q+2]] * p2[4*q+2]));
        v.w = fmaf(w0[KL[4*q+3]], cv.w, fmaf(w1[KL[4*q+3]], p1[4*q+3], w2[KL[4*q+3]] * p2[4*q+3]));
        *reinterpret_cast<float4*>(op + 4 * q) = v;
    }
}

// ---------------------------------------------------------------------------
extern "C" void kernel_launch(void* const* d_in, const int* in_sizes, int n_in,
                              void* d_out, int out_size) {
    // Bind inputs BY SIZE: feat = largest (n*128*36), W = 23040, atype = n*10
    const float* feat  = nullptr;
    const float* atype = nullptr;
    const float* W     = nullptr;

    int fi = 0;
    for (int i = 1; i < n_in; ++i) if (in_sizes[i] > in_sizes[fi]) fi = i;
    feat = (const float*)d_in[fi];
    int n_atoms = in_sizes[fi] / (NCH * DIM);

    for (int i = 0; i < n_in; ++i) {
        if (i == fi) continue;
        if (in_sizes[i] == WSIZE && W == nullptr && in_sizes[i] != n_atoms * NTYPE) {
            W = (const float*)d_in[i];
        } else if (in_sizes[i] == n_atoms * NTYPE && atype == nullptr) {
            atype = (const float*)d_in[i];
        } else if (W == nullptr) {
            W = (const float*)d_in[i];
        } else {
            atype = (const float*)d_in[i];
        }
    }
    if (!atype) atype = (const float*)d_in[1];
    if (!W)     W     = (const float*)d_in[2];

    float* out = (float*)d_out;

    // smem: 1024 floats header + 144*128 fp16 fg = 4096 + 36864 = 40960 B
    size_t smem = 1024 * sizeof(float) + (size_t)NBETA * NALPHA * NCH * sizeof(__half);
    cudaFuncSetAttribute(tp_main_kernel,
                         cudaFuncAttributeMaxDynamicSharedMemorySize, (int)smem);

    init_tables_kernel<<<1, 32>>>();
    tp_main_kernel<<<n_atoms, NCH, smem>>>(feat, atype, W, out);
}

// round 7
// speedup vs baseline: 1.1679x; 1.1679x over previous
#include <cuda_runtime.h>
#include <cuda_fp16.h>
#include <math.h>

#ifndef M_PI
#define M_PI 3.14159265358979323846
#endif

#define NBETA   12
#define NALPHA  12
#define DIM     36
#define NCH     128
#define NTYPE   10
#define WSIZE   (3 * NTYPE * NCH * 6)   // 23040

// ---- hard-coded 12-point Gauss-Legendre nodes/weights ----
__constant__ double c_glx[NBETA] = {
    -0.9815606342467192, -0.9041172563704749, -0.7699026741943047,
    -0.5873179542866175, -0.3678314989981802, -0.1252334085114689,
     0.1252334085114689,  0.3678314989981802,  0.5873179542866175,
     0.7699026741943047,  0.9041172563704749,  0.9815606342467192
};
__constant__ double c_glw[NBETA] = {
    0.0471753363865118, 0.1069393259953184, 0.1600783285433462,
    0.2031674267230659, 0.2334925365383548, 0.2491470458134028,
    0.2491470458134028, 0.2334925365383548, 0.2031674267230659,
    0.1600783285433462, 0.1069393259953184, 0.0471753363865118
};

// Packed factored tables (single strided load in main kernel):
//   [0,432) Pk   [432,864) Pwk   [864,1008) ang (a*12+mi, [11] pad)
#define TBL_PK   0
#define TBL_PW   432
#define TBL_ANG  864
#define TBL_SIZE 1008
__device__ float g_tbl[TBL_SIZE];

__global__ void init_tables_kernel() {
    int t = threadIdx.x;
    if (t < NBETA) {
        double x = c_glx[t];
        double w = c_glw[t];
        double P[6][6];
        double s = sqrt(fmax(1.0 - x * x, 0.0));
        P[0][0] = sqrt(1.0 / (4.0 * M_PI));
        for (int m = 1; m <= 5; ++m)
            P[m][m] = sqrt((2.0 * m + 1.0) / (2.0 * m)) * s * P[m - 1][m - 1];
        for (int m = 0; m < 5; ++m)
            P[m + 1][m] = sqrt(2.0 * m + 3.0) * x * P[m][m];
        for (int m = 0; m <= 5; ++m)
            for (int l = m + 2; l <= 5; ++l) {
                double aa = sqrt((4.0 * l * l - 1.0) / ((double)l * l - (double)m * m));
                double bb = sqrt((((l - 1.0) * (l - 1.0)) - (double)m * m) /
                                 (4.0 * (l - 1.0) * (l - 1.0) - 1.0));
                P[l][m] = aa * (x * P[l - 1][m] - bb * P[l - 2][m]);
            }
        double wfac = w * (2.0 * M_PI / (double)NALPHA);
        for (int k = 0; k < DIM; ++k) {
            int l = 0;
            while (k >= (l + 1) * (l + 1)) ++l;
            int m = k - l * l - l;
            double v = P[l][m < 0 ? -m : m];
            g_tbl[TBL_PK + t * DIM + k] = (float)v;
            g_tbl[TBL_PW + t * DIM + k] = (float)(v * wfac);
        }
    } else if (t < NBETA + NALPHA) {
        int a = t - NBETA;
        double alpha = a * (2.0 * M_PI / (double)NALPHA);
        double s2 = sqrt(2.0);
        for (int mi = 0; mi < 12; ++mi) g_tbl[TBL_ANG + a * 12 + mi] = 0.0f;
        g_tbl[TBL_ANG + a * 12 + 5] = 1.0f;
        for (int m = 1; m <= 5; ++m) {
            g_tbl[TBL_ANG + a * 12 + 5 + m] = (float)(s2 * cos(m * alpha));
            g_tbl[TBL_ANG + a * 12 + 5 - m] = (float)(s2 * sin(m * alpha));
        }
    }
}

// ---------------------------------------------------------------------------
// Main kernel: block = 1 atom, thread = 1 channel.
// fp16 fg cache; weights deferred; c0 reloaded for combine.
// launch_bounds (128, 3): 168-reg cap — fits the ~130-reg live set without
// spilling (round 6's 128-reg cap spilled p1/p2 → L2 46%, regression).
// ---------------------------------------------------------------------------
__global__ __launch_bounds__(NCH, 3) void tp_main_kernel(
    const float* __restrict__ feat,    // [n, 128, 36]
    const float* __restrict__ atype,   // [n, 10]
    const float* __restrict__ W,       // [3, 10, 128, 6]
    float* __restrict__ out)           // [n, 128, 36]
{
    constexpr int KM[DIM] = {5,
                             4,5,6,
                             3,4,5,6,7,
                             2,3,4,5,6,7,8,
                             1,2,3,4,5,6,7,8,9,
                             0,1,2,3,4,5,6,7,8,9,10};
    constexpr int KL[DIM] = {0,
                             1,1,1,
                             2,2,2,2,2,
                             3,3,3,3,3,3,3,
                             4,4,4,4,4,4,4,4,4,
                             5,5,5,5,5,5,5,5,5,5,5};

    extern __shared__ float sm[];
    float*  sPk  = sm + TBL_PK;    // 432
    float*  sPw  = sm + TBL_PW;    // 432
    float*  sAng = sm + TBL_ANG;   // 144
    float*  sAt  = sm + TBL_SIZE;  // 16 (pad to 1024 floats)
    __half* sFg  = reinterpret_cast<__half*>(sm + 1024);  // 144*128 fp16

    const int tid = threadIdx.x;
    const int n   = blockIdx.x;

    for (int i = tid; i < TBL_SIZE; i += NCH) sm[i] = g_tbl[i];
    if (tid < NTYPE) sAt[tid] = atype[(size_t)n * NTYPE + tid];
    __syncthreads();

    const size_t base = ((size_t)n * NCH + tid) * DIM;

    // ---- load coefficients ----
    float c0[DIM];
    {
        const float4* fp = reinterpret_cast<const float4*>(feat + base);
        #pragma unroll
        for (int q = 0; q < 9; ++q) {
            float4 v = fp[q];
            c0[4*q+0] = v.x; c0[4*q+1] = v.y; c0[4*q+2] = v.z; c0[4*q+3] = v.w;
        }
    }

    // =================== pass A: fg = Y c0 ; p1 = Yw^T (fg*fg) ===============
    float p1[DIM];
    #pragma unroll
    for (int k = 0; k < DIM; ++k) p1[k] = 0.f;

    #pragma unroll 1
    for (int b = 0; b < NBETA; ++b) {
        float t[11];
        #pragma unroll
        for (int mi = 0; mi < 11; ++mi) t[mi] = 0.f;
        #pragma unroll
        for (int k = 0; k < DIM; ++k)
            t[KM[k]] = fmaf(sPk[b * DIM + k], c0[k], t[KM[k]]);

        float u[11];
        #pragma unroll
        for (int mi = 0; mi < 11; ++mi) u[mi] = 0.f;
        #pragma unroll
        for (int a = 0; a < NALPHA; ++a) {
            const float* an = sAng + a * 12;
            float f = t[0] * an[0];
            #pragma unroll
            for (int mi = 1; mi < 11; ++mi) f = fmaf(t[mi], an[mi], f);
            sFg[(b * NALPHA + a) * NCH + tid] = __float2half(f);
            float g = f * f;                 // exact f in pass A
            #pragma unroll
            for (int mi = 0; mi < 11; ++mi) u[mi] = fmaf(g, an[mi], u[mi]);
        }
        #pragma unroll
        for (int k = 0; k < DIM; ++k)
            p1[k] = fmaf(sPw[b * DIM + k], u[KM[k]], p1[k]);
    }
    // c0 dead here (reloaded for combine)

    // ============ pass B: p2 = Yw^T ((Y p1) * fg) ============================
    float p2[DIM];
    #pragma unroll
    for (int k = 0; k < DIM; ++k) p2[k] = 0.f;

    #pragma unroll 1
    for (int b = 0; b < NBETA; ++b) {
        float t[11];
        #pragma unroll
        for (int mi = 0; mi < 11; ++mi) t[mi] = 0.f;
        #pragma unroll
        for (int k = 0; k < DIM; ++k)
            t[KM[k]] = fmaf(sPk[b * DIM + k], p1[k], t[KM[k]]);

        float u[11];
        #pragma unroll
        for (int mi = 0; mi < 11; ++mi) u[mi] = 0.f;
        #pragma unroll
        for (int a = 0; a < NALPHA; ++a) {
            const float* an = sAng + a * 12;
            float f = t[0] * an[0];
            #pragma unroll
            for (int mi = 1; mi < 11; ++mi) f = fmaf(t[mi], an[mi], f);
            float g = f * __half2float(sFg[(b * NALPHA + a) * NCH + tid]);
            #pragma unroll
            for (int mi = 0; mi < 11; ++mi) u[mi] = fmaf(g, an[mi], u[mi]);
        }
        #pragma unroll
        for (int k = 0; k < DIM; ++k)
            p2[k] = fmaf(sPw[b * DIM + k], u[KM[k]], p2[k]);
    }

    // ---- weights (deferred to keep them out of the hot passes) ----
    float w0[6], w1[6], w2[6];
    #pragma unroll
    for (int l = 0; l < 6; ++l) { w0[l] = 0.f; w1[l] = 0.f; w2[l] = 0.f; }
    #pragma unroll 1
    for (int e = 0; e < NTYPE; ++e) {
        float a = sAt[e];
        const float* Wp = W + ((size_t)e * NCH + tid) * 6;
        #pragma unroll
        for (int l = 0; l < 6; ++l) {
            w0[l] = fmaf(a, Wp[l],                       w0[l]);
            w1[l] = fmaf(a, Wp[NTYPE * NCH * 6 + l],     w1[l]);
            w2[l] = fmaf(a, Wp[2 * NTYPE * NCH * 6 + l], w2[l]);
        }
    }

    // ---- final combine: reload c0 (L2 hit) + vectorized store ----
    const float4* fp = reinterpret_cast<const float4*>(feat + base);
    float* op = out + base;
    #pragma unroll
    for (int q = 0; q < 9; ++q) {
        float4 cv = fp[q];
        float4 v;
        v.x = fmaf(w0[KL[4*q+0]], cv.x, fmaf(w1[KL[4*q+0]], p1[4*q+0], w2[KL[4*q+0]] * p2[4*q+0]));
        v.y = fmaf(w0[KL[4*q+1]], cv.y, fmaf(w1[KL[4*q+1]], p1[4*q+1], w2[KL[4*q+1]] * p2[4*q+1]));
        v.z = fmaf(w0[KL[4*q+2]], cv.z, fmaf(w1[KL[4*q+2]], p1[4*q+2], w2[KL[4*q+2]] * p2[4*q+2]));
        v.w = fmaf(w0[KL[4*q+3]], cv.w, fmaf(w1[KL[4*q+3]], p1[4*q+3], w2[KL[4*q+3]] * p2[4*q+3]));
        *reinterpret_cast<float4*>(op + 4 * q) = v;
    }
}

// ---------------------------------------------------------------------------
extern "C" void kernel_launch(void* const* d_in, const int* in_sizes, int n_in,
                              void* d_out, int out_size) {
    // Bind inputs BY SIZE: feat = largest (n*128*36), W = 23040, atype = n*10
    const float* feat  = nullptr;
    const float* atype = nullptr;
    const float* W     = nullptr;

    int fi = 0;
    for (int i = 1; i < n_in; ++i) if (in_sizes[i] > in_sizes[fi]) fi = i;
    feat = (const float*)d_in[fi];
    int n_atoms = in_sizes[fi] / (NCH * DIM);

    for (int i = 0; i < n_in; ++i) {
        if (i == fi) continue;
        if (in_sizes[i] == WSIZE && W == nullptr && in_sizes[i] != n_atoms * NTYPE) {
            W = (const float*)d_in[i];
        } else if (in_sizes[i] == n_atoms * NTYPE && atype == nullptr) {
            atype = (const float*)d_in[i];
        } else if (W == nullptr) {
            W = (const float*)d_in[i];
        } else {
            atype = (const float*)d_in[i];
        }
    }
    if (!atype) atype = (const float*)d_in[1];
    if (!W)     W     = (const float*)d_in[2];

    float* out = (float*)d_out;

    // smem: 1024 floats header + 144*128 fp16 fg = 4096 + 36864 = 40960 B
    size_t smem = 1024 * sizeof(float) + (size_t)NBETA * NALPHA * NCH * sizeof(__half);
    cudaFuncSetAttribute(tp_main_kernel,
                         cudaFuncAttributeMaxDynamicSharedMemorySize, (int)smem);

    init_tables_kernel<<<1, 32>>>();
    tp_main_kernel<<<n_atoms, NCH, smem>>>(feat, atype, W, out);
}

// round 8
// speedup vs baseline: 1.4852x; 1.2716x over previous
#include <cuda_runtime.h>
#include <math.h>

#ifndef M_PI
#define M_PI 3.14159265358979323846
#endif

#define NBETA   12
#define NALPHA  12
#define NAPAIR  6            // alpha pairs (a, a+6)
#define DIM     36
#define NCH     128
#define NTYPE   10
#define WSIZE   (3 * NTYPE * NCH * 6)   // 23040

// ---- hard-coded 12-point Gauss-Legendre nodes/weights ----
__constant__ double c_glx[NBETA] = {
    -0.9815606342467192, -0.9041172563704749, -0.7699026741943047,
    -0.5873179542866175, -0.3678314989981802, -0.1252334085114689,
     0.1252334085114689,  0.3678314989981802,  0.5873179542866175,
     0.7699026741943047,  0.9041172563704749,  0.9815606342467192
};
__constant__ double c_glw[NBETA] = {
    0.0471753363865118, 0.1069393259953184, 0.1600783285433462,
    0.2031674267230659, 0.2334925365383548, 0.2491470458134028,
    0.2491470458134028, 0.2334925365383548, 0.2031674267230659,
    0.1600783285433462, 0.1069393259953184, 0.0471753363865118
};

// Packed factored tables:
//   [0,432) Pk   [432,864) Pwk   [864,1008) ang (a*12+mi, [11] pad)
#define TBL_PK   0
#define TBL_PW   432
#define TBL_ANG  864
#define TBL_SIZE 1008
__device__ float g_tbl[TBL_SIZE];

__global__ void init_tables_kernel() {
    int t = threadIdx.x;
    if (t < NBETA) {
        double x = c_glx[t];
        double w = c_glw[t];
        double P[6][6];
        double s = sqrt(fmax(1.0 - x * x, 0.0));
        P[0][0] = sqrt(1.0 / (4.0 * M_PI));
        for (int m = 1; m <= 5; ++m)
            P[m][m] = sqrt((2.0 * m + 1.0) / (2.0 * m)) * s * P[m - 1][m - 1];
        for (int m = 0; m < 5; ++m)
            P[m + 1][m] = sqrt(2.0 * m + 3.0) * x * P[m][m];
        for (int m = 0; m <= 5; ++m)
            for (int l = m + 2; l <= 5; ++l) {
                double aa = sqrt((4.0 * l * l - 1.0) / ((double)l * l - (double)m * m));
                double bb = sqrt((((l - 1.0) * (l - 1.0)) - (double)m * m) /
                                 (4.0 * (l - 1.0) * (l - 1.0) - 1.0));
                P[l][m] = aa * (x * P[l - 1][m] - bb * P[l - 2][m]);
            }
        double wfac = w * (2.0 * M_PI / (double)NALPHA);
        for (int k = 0; k < DIM; ++k) {
            int l = 0;
            while (k >= (l + 1) * (l + 1)) ++l;
            int m = k - l * l - l;
            double v = P[l][m < 0 ? -m : m];
            g_tbl[TBL_PK + t * DIM + k] = (float)v;
            g_tbl[TBL_PW + t * DIM + k] = (float)(v * wfac);
        }
    } else if (t < NBETA + NALPHA) {
        int a = t - NBETA;
        double alpha = a * (2.0 * M_PI / (double)NALPHA);
        double s2 = sqrt(2.0);
        for (int mi = 0; mi < 12; ++mi) g_tbl[TBL_ANG + a * 12 + mi] = 0.0f;
        g_tbl[TBL_ANG + a * 12 + 5] = 1.0f;
        for (int m = 1; m <= 5; ++m) {
            g_tbl[TBL_ANG + a * 12 + 5 + m] = (float)(s2 * cos(m * alpha));
            g_tbl[TBL_ANG + a * 12 + 5 - m] = (float)(s2 * sin(m * alpha));
        }
    }
}

// m-parity index sets (mi = m+5):
//   even m  -> mi odd  : {1,3,5,7,9}   (5 terms)  -- sign-invariant under alpha+pi
//   odd  m  -> mi even : {0,2,4,6,8,10} (6 terms) -- sign-flipped  under alpha+pi
#define FE_SUM(t, an) (fmaf((t)[1],(an)[1], fmaf((t)[3],(an)[3], fmaf((t)[5],(an)[5], \
                      fmaf((t)[7],(an)[7], (t)[9]*(an)[9])))))
#define FO_SUM(t, an) (fmaf((t)[0],(an)[0], fmaf((t)[2],(an)[2], fmaf((t)[4],(an)[4], \
                      fmaf((t)[6],(an)[6], fmaf((t)[8],(an)[8], (t)[10]*(an)[10]))))))
#define U_ACC(u, an, gs, gd) do { \
    (u)[1] = fmaf((gs),(an)[1],(u)[1]); (u)[3] = fmaf((gs),(an)[3],(u)[3]); \
    (u)[5] = fmaf((gs),(an)[5],(u)[5]); (u)[7] = fmaf((gs),(an)[7],(u)[7]); \
    (u)[9] = fmaf((gs),(an)[9],(u)[9]); \
    (u)[0] = fmaf((gd),(an)[0],(u)[0]); (u)[2] = fmaf((gd),(an)[2],(u)[2]); \
    (u)[4] = fmaf((gd),(an)[4],(u)[4]); (u)[6] = fmaf((gd),(an)[6],(u)[6]); \
    (u)[8] = fmaf((gd),(an)[8],(u)[8]); (u)[10] = fmaf((gd),(an)[10],(u)[10]); \
} while (0)

// ---------------------------------------------------------------------------
// Main kernel: block = 1 atom, thread = 1 channel. Round-5 structure
// (255 regs, 2 blocks/SM, zero spills) + alpha-pair symmetry (~29% fewer ops).
// ---------------------------------------------------------------------------
__global__ __launch_bounds__(NCH) void tp_main_kernel(
    const float* __restrict__ feat,    // [n, 128, 36]
    const float* __restrict__ atype,   // [n, 10]
    const float* __restrict__ W,       // [3, 10, 128, 6]
    float* __restrict__ out)           // [n, 128, 36]
{
    constexpr int KM[DIM] = {5,
                             4,5,6,
                             3,4,5,6,7,
                             2,3,4,5,6,7,8,
                             1,2,3,4,5,6,7,8,9,
                             0,1,2,3,4,5,6,7,8,9,10};
    constexpr int KL[DIM] = {0,
                             1,1,1,
                             2,2,2,2,2,
                             3,3,3,3,3,3,3,
                             4,4,4,4,4,4,4,4,4,
                             5,5,5,5,5,5,5,5,5,5,5};

    extern __shared__ float sm[];
    float*  sPk  = sm + TBL_PK;    // 432
    float*  sPw  = sm + TBL_PW;    // 432
    float*  sAng = sm + TBL_ANG;   // 144 (only rows 0..5 used in hot loops)
    float*  sAt  = sm + TBL_SIZE;  // pad to 1024 floats
    float2* sFg  = reinterpret_cast<float2*>(sm + 1024);  // [b*6+ap][tid] (f_a, f_{a+6})

    const int tid = threadIdx.x;
    const int n   = blockIdx.x;

    for (int i = tid; i < TBL_SIZE; i += NCH) sm[i] = g_tbl[i];
    if (tid < NTYPE) sAt[tid] = atype[(size_t)n * NTYPE + tid];
    __syncthreads();

    const size_t base = ((size_t)n * NCH + tid) * DIM;

    // ---- load coefficients ----
    float c0[DIM];
    {
        const float4* fp = reinterpret_cast<const float4*>(feat + base);
        #pragma unroll
        for (int q = 0; q < 9; ++q) {
            float4 v = fp[q];
            c0[4*q+0] = v.x; c0[4*q+1] = v.y; c0[4*q+2] = v.z; c0[4*q+3] = v.w;
        }
    }

    // ---- atom-type-weighted per-l weights ----
    float w0[6], w1[6], w2[6];
    #pragma unroll
    for (int l = 0; l < 6; ++l) { w0[l] = 0.f; w1[l] = 0.f; w2[l] = 0.f; }
    #pragma unroll 1
    for (int e = 0; e < NTYPE; ++e) {
        float a = sAt[e];
        const float* Wp = W + ((size_t)e * NCH + tid) * 6;
        #pragma unroll
        for (int l = 0; l < 6; ++l) {
            w0[l] = fmaf(a, Wp[l],                       w0[l]);
            w1[l] = fmaf(a, Wp[NTYPE * NCH * 6 + l],     w1[l]);
            w2[l] = fmaf(a, Wp[2 * NTYPE * NCH * 6 + l], w2[l]);
        }
    }

    // =================== pass A: fg = Y c0 ; p1 = Yw^T (fg*fg) ===============
    float p1[DIM];
    #pragma unroll
    for (int k = 0; k < DIM; ++k) p1[k] = 0.f;

    #pragma unroll 1
    for (int b = 0; b < NBETA; ++b) {
        float t[11];
        #pragma unroll
        for (int mi = 0; mi < 11; ++mi) t[mi] = 0.f;
        #pragma unroll
        for (int k = 0; k < DIM; ++k)
            t[KM[k]] = fmaf(sPk[b * DIM + k], c0[k], t[KM[k]]);

        float u[11];
        #pragma unroll
        for (int mi = 0; mi < 11; ++mi) u[mi] = 0.f;
        #pragma unroll
        for (int ap = 0; ap < NAPAIR; ++ap) {
            const float* an = sAng + ap * 12;
            float fe = FE_SUM(t, an);       // even-m part (invariant under +pi)
            float fo = FO_SUM(t, an);       // odd-m part  (flips under +pi)
            float f1 = fe + fo;             // f at alpha_a
            float f2 = fe - fo;             // f at alpha_{a+6}
            sFg[(b * NAPAIR + ap) * NCH + tid] = make_float2(f1, f2);
            float g1 = f1 * f1, g2 = f2 * f2;
            float gs = g1 + g2, gd = g1 - g2;
            U_ACC(u, an, gs, gd);
        }
        #pragma unroll
        for (int k = 0; k < DIM; ++k)
            p1[k] = fmaf(sPw[b * DIM + k], u[KM[k]], p1[k]);
    }

    // fold nu=0 and nu=1 contributions
    float acc[DIM];
    #pragma unroll
    for (int k = 0; k < DIM; ++k)
        acc[k] = w0[KL[k]] * c0[k] + w1[KL[k]] * p1[k];

    // ============ pass B: p2 = Yw^T ((Y p1) * fg) ============================
    float p2[DIM];
    #pragma unroll
    for (int k = 0; k < DIM; ++k) p2[k] = 0.f;

    #pragma unroll 1
    for (int b = 0; b < NBETA; ++b) {
        float t[11];
        #pragma unroll
        for (int mi = 0; mi < 11; ++mi) t[mi] = 0.f;
        #pragma unroll
        for (int k = 0; k < DIM; ++k)
            t[KM[k]] = fmaf(sPk[b * DIM + k], p1[k], t[KM[k]]);

        float u[11];
        #pragma unroll
        for (int mi = 0; mi < 11; ++mi) u[mi] = 0.f;
        #pragma unroll
        for (int ap = 0; ap < NAPAIR; ++ap) {
            const float* an = sAng + ap * 12;
            float fe = FE_SUM(t, an);
            float fo = FO_SUM(t, an);
            float2 fg = sFg[(b * NAPAIR + ap) * NCH + tid];
            float g1 = (fe + fo) * fg.x;
            float g2 = (fe - fo) * fg.y;
            float gs = g1 + g2, gd = g1 - g2;
            U_ACC(u, an, gs, gd);
        }
        #pragma unroll
        for (int k = 0; k < DIM; ++k)
            p2[k] = fmaf(sPw[b * DIM + k], u[KM[k]], p2[k]);
    }

    // ---- final combine + vectorized store ----
    float* op = out + base;
    #pragma unroll
    for (int q = 0; q < 9; ++q) {
        float4 v;
        v.x = fmaf(w2[KL[4*q+0]], p2[4*q+0], acc[4*q+0]);
        v.y = fmaf(w2[KL[4*q+1]], p2[4*q+1], acc[4*q+1]);
        v.z = fmaf(w2[KL[4*q+2]], p2[4*q+2], acc[4*q+2]);
        v.w = fmaf(w2[KL[4*q+3]], p2[4*q+3], acc[4*q+3]);
        *reinterpret_cast<float4*>(op + 4 * q) = v;
    }
}

// ---------------------------------------------------------------------------
extern "C" void kernel_launch(void* const* d_in, const int* in_sizes, int n_in,
                              void* d_out, int out_size) {
    // Bind inputs BY SIZE: feat = largest (n*128*36), W = 23040, atype = n*10
    const float* feat  = nullptr;
    const float* atype = nullptr;
    const float* W     = nullptr;

    int fi = 0;
    for (int i = 1; i < n_in; ++i) if (in_sizes[i] > in_sizes[fi]) fi = i;
    feat = (const float*)d_in[fi];
    int n_atoms = in_sizes[fi] / (NCH * DIM);

    for (int i = 0; i < n_in; ++i) {
        if (i == fi) continue;
        if (in_sizes[i] == WSIZE && W == nullptr && in_sizes[i] != n_atoms * NTYPE) {
            W = (const float*)d_in[i];
        } else if (in_sizes[i] == n_atoms * NTYPE && atype == nullptr) {
            atype = (const float*)d_in[i];
        } else if (W == nullptr) {
            W = (const float*)d_in[i];
        } else {
            atype = (const float*)d_in[i];
        }
    }
    if (!atype) atype = (const float*)d_in[1];
    if (!W)     W     = (const float*)d_in[2];

    float* out = (float*)d_out;

    // smem: 1024-float header + 144*128 float fg (as float2 pairs) = 77824 B
    size_t smem = (size_t)(1024 + NBETA * NALPHA * NCH) * sizeof(float);
    cudaFuncSetAttribute(tp_main_kernel,
                         cudaFuncAttributeMaxDynamicSharedMemorySize, (int)smem);

    init_tables_kernel<<<1, 32>>>();
    tp_main_kernel<<<n_atoms, NCH, smem>>>(feat, atype, W, out);
}

// round 9
// speedup vs baseline: 1.9616x; 1.3208x over previous
#include <cuda_runtime.h>
#include <math.h>

#ifndef M_PI
#define M_PI 3.14159265358979323846
#endif

#define NBETA   12
#define NAPAIR  6
#define NALPHA  12
#define DIM     36
#define NCH     128
#define NTYPE   10
#define WSIZE   (3 * NTYPE * NCH * 6)   // 23040

typedef unsigned long long ull;

// ---- packed f32x2 helpers (FFMA2 path; ptxas never emits these from C++) ----
__device__ __forceinline__ ull pk2(float lo, float hi) {
    ull r; asm("mov.b64 %0, {%1, %2};" : "=l"(r) : "f"(lo), "f"(hi)); return r;
}
__device__ __forceinline__ void upk2(ull v, float& lo, float& hi) {
    asm("mov.b64 {%0, %1}, %2;" : "=f"(lo), "=f"(hi) : "l"(v));
}
__device__ __forceinline__ ull fma2(ull a, ull b, ull c) {
    ull d; asm("fma.rn.f32x2 %0, %1, %2, %3;" : "=l"(d) : "l"(a), "l"(b), "l"(c)); return d;
}
__device__ __forceinline__ ull add2(ull a, ull b) {
    ull d; asm("add.rn.f32x2 %0, %1, %2;" : "=l"(d) : "l"(a), "l"(b)); return d;
}

// ---- 12-point Gauss-Legendre nodes/weights ----
__constant__ double c_glx[NBETA] = {
    -0.9815606342467192, -0.9041172563704749, -0.7699026741943047,
    -0.5873179542866175, -0.3678314989981802, -0.1252334085114689,
     0.1252334085114689,  0.3678314989981802,  0.5873179542866175,
     0.7699026741943047,  0.9041172563704749,  0.9815606342467192
};
__constant__ double c_glw[NBETA] = {
    0.0471753363865118, 0.1069393259953184, 0.1600783285433462,
    0.2031674267230659, 0.2334925365383548, 0.2491470458134028,
    0.2491470458134028, 0.2334925365383548, 0.2031674267230659,
    0.1600783285433462, 0.1069393259953184, 0.0471753363865118
};

// Pair table for the l<->m contractions. Each entry i: lane.lo uses k=PKA[i]
// (mi even = 2*PJT[i]), lane.hi uses k=PKB[i] (mi odd = 2*PJT[i]+1); -1 = zero lane.
// Covers all 36 k exactly once (15 true pairs + 6 half pairs).
__constant__ int PKA[21] = {25,-1, 9,17,27,-1, 1, 5,11,19,29,-1, 3, 7,13,21,31,15,23,33,35};
__constant__ int PKB[21] = {16,26, 4,10,18,28, 0, 2, 6,12,20,30, 8,14,22,32,-1,24,34,-1,-1};
__constant__ int PJT[21] = { 0, 0, 1, 1, 1, 1, 2, 2, 2, 2, 2, 2, 3, 3, 3, 3, 3, 4, 4, 4, 5};

// Device table layout (floats):
//   [0,432)     Pw  scalar  Pwk[b][k]
//   [432,960)   PKP packed  12 b x 22 entries x 2 (entry 21 = zero pad; 176 B/row)
//   [960,1032)  AN2 packed  6 ap x 6 packs x 2 ((ang[2j],ang[2j+1]), pack5=(ang[10],0))
#define OFF_PW   0
#define OFF_PKP  432
#define OFF_AN2  960
#define TBL_SIZE 1032
#define OFF_AT   1032          // atype staging in smem only
#define HDR      1048          // header floats (16B aligned end)
__device__ float g_tbl[TBL_SIZE];

__global__ void init_tables_kernel() {
    int t = threadIdx.x;
    if (t < NBETA) {
        double x = c_glx[t];
        double w = c_glw[t];
        double P[6][6];
        double s = sqrt(fmax(1.0 - x * x, 0.0));
        P[0][0] = sqrt(1.0 / (4.0 * M_PI));
        for (int m = 1; m <= 5; ++m)
            P[m][m] = sqrt((2.0 * m + 1.0) / (2.0 * m)) * s * P[m - 1][m - 1];
        for (int m = 0; m < 5; ++m)
            P[m + 1][m] = sqrt(2.0 * m + 3.0) * x * P[m][m];
        for (int m = 0; m <= 5; ++m)
            for (int l = m + 2; l <= 5; ++l) {
                double aa = sqrt((4.0 * l * l - 1.0) / ((double)l * l - (double)m * m));
                double bb = sqrt((((l - 1.0) * (l - 1.0)) - (double)m * m) /
                                 (4.0 * (l - 1.0) * (l - 1.0) - 1.0));
                P[l][m] = aa * (x * P[l - 1][m] - bb * P[l - 2][m]);
            }
        double wfac = w * (2.0 * M_PI / (double)NALPHA);
        float Pk[DIM];
        for (int k = 0; k < DIM; ++k) {
            int l = 0;
            while (k >= (l + 1) * (l + 1)) ++l;
            int m = k - l * l - l;
            double v = P[l][m < 0 ? -m : m];
            Pk[k] = (float)v;
            g_tbl[OFF_PW + t * DIM + k] = (float)(v * wfac);
        }
        for (int i = 0; i < 21; ++i) {
            int kA = PKA[i], kB = PKB[i];
            g_tbl[OFF_PKP + t * 44 + 2 * i + 0] = (kA >= 0) ? Pk[kA] : 0.0f;
            g_tbl[OFF_PKP + t * 44 + 2 * i + 1] = (kB >= 0) ? Pk[kB] : 0.0f;
        }
        g_tbl[OFF_PKP + t * 44 + 42] = 0.0f;   // pad entry 21
        g_tbl[OFF_PKP + t * 44 + 43] = 0.0f;
    } else if (t < NBETA + NAPAIR) {
        int a = t - NBETA;
        double alpha = a * (2.0 * M_PI / (double)NALPHA);
        double s2 = sqrt(2.0);
        float ang[11];
        ang[5] = 1.0f;
        for (int m = 1; m <= 5; ++m) {
            ang[5 + m] = (float)(s2 * cos(m * alpha));
            ang[5 - m] = (float)(s2 * sin(m * alpha));
        }
        for (int j = 0; j < 5; ++j) {
            g_tbl[OFF_AN2 + a * 12 + 2 * j + 0] = ang[2 * j];
            g_tbl[OFF_AN2 + a * 12 + 2 * j + 1] = ang[2 * j + 1];
        }
        g_tbl[OFF_AN2 + a * 12 + 10] = ang[10];
        g_tbl[OFF_AN2 + a * 12 + 11] = 0.0f;
    }
}

// ---------------------------------------------------------------------------
// Main kernel: block = 1 atom, thread = 1 channel.
// Hot loops run on packed f32x2 FMA (FFMA2). alpha-pair symmetry retained.
// ---------------------------------------------------------------------------
__global__ __launch_bounds__(NCH) void tp_main_kernel(
    const float* __restrict__ feat,    // [n, 128, 36]
    const float* __restrict__ atype,   // [n, 10]
    const float* __restrict__ W,       // [3, 10, 128, 6]
    float* __restrict__ out)           // [n, 128, 36]
{
    constexpr int KA[21] = {25,-1, 9,17,27,-1, 1, 5,11,19,29,-1, 3, 7,13,21,31,15,23,33,35};
    constexpr int KB[21] = {16,26, 4,10,18,28, 0, 2, 6,12,20,30, 8,14,22,32,-1,24,34,-1,-1};
    constexpr int JT[21] = { 0, 0, 1, 1, 1, 1, 2, 2, 2, 2, 2, 2, 3, 3, 3, 3, 3, 4, 4, 4, 5};
    constexpr int KM[DIM] = {5,
                             4,5,6,
                             3,4,5,6,7,
                             2,3,4,5,6,7,8,
                             1,2,3,4,5,6,7,8,9,
                             0,1,2,3,4,5,6,7,8,9,10};
    constexpr int KL[DIM] = {0,
                             1,1,1,
                             2,2,2,2,2,
                             3,3,3,3,3,3,3,
                             4,4,4,4,4,4,4,4,4,
                             5,5,5,5,5,5,5,5,5,5,5};

    extern __shared__ float sm[];
    float*  sPw  = sm + OFF_PW;
    float*  sAt  = sm + OFF_AT;
    float2* sFg  = reinterpret_cast<float2*>(sm + HDR);   // [b*6+ap][tid]

    const int tid = threadIdx.x;
    const int n   = blockIdx.x;

    for (int i = tid; i < TBL_SIZE; i += NCH) sm[i] = g_tbl[i];
    if (tid < NTYPE) sAt[tid] = atype[(size_t)n * NTYPE + tid];
    __syncthreads();

    const size_t base = ((size_t)n * NCH + tid) * DIM;

    // ---- load coefficients and build packed operand set for pass A ----
    ull cpk[21];
    {
        float c0[DIM];
        const float4* fp = reinterpret_cast<const float4*>(feat + base);
        #pragma unroll
        for (int q = 0; q < 9; ++q) {
            float4 v = fp[q];
            c0[4*q+0] = v.x; c0[4*q+1] = v.y; c0[4*q+2] = v.z; c0[4*q+3] = v.w;
        }
        #pragma unroll
        for (int i = 0; i < 21; ++i)
            cpk[i] = pk2(KA[i] >= 0 ? c0[KA[i]] : 0.0f,
                         KB[i] >= 0 ? c0[KB[i]] : 0.0f);
    }

    const ulonglong2* anr = reinterpret_cast<const ulonglong2*>(sm + OFF_AN2);

    // =================== pass A: fg = Y c0 ; p1 = Yw^T (fg*fg) ===============
    float p1[DIM];
    #pragma unroll
    for (int k = 0; k < DIM; ++k) p1[k] = 0.f;

    #pragma unroll 1
    for (int b = 0; b < NBETA; ++b) {
        const ulonglong2* pr = reinterpret_cast<const ulonglong2*>(sm + OFF_PKP + b * 44);
        ull pk[22];
        #pragma unroll
        for (int i = 0; i < 11; ++i) { ulonglong2 v = pr[i]; pk[2*i] = v.x; pk[2*i+1] = v.y; }

        ull t2[6] = {0,0,0,0,0,0};
        #pragma unroll
        for (int i = 0; i < 21; ++i) t2[JT[i]] = fma2(pk[i], cpk[i], t2[JT[i]]);

        ull u2[6] = {0,0,0,0,0,0};
        #pragma unroll
        for (int ap = 0; ap < NAPAIR; ++ap) {
            ulonglong2 a01 = anr[ap*3+0], a23 = anr[ap*3+1], a45 = anr[ap*3+2];
            // two chains for ILP, then packed add: lanes = (fo, fe)
            ull sA = fma2(t2[2], a23.x, fma2(t2[1], a01.y, fma2(t2[0], a01.x, 0ULL)));
            ull sB = fma2(t2[5], a45.y, fma2(t2[4], a45.x, fma2(t2[3], a23.y, 0ULL)));
            ull sfo_fe = add2(sA, sB);
            float fo, fe; upk2(sfo_fe, fo, fe);
            float f1 = fe + fo, f2 = fe - fo;
            sFg[(b * NAPAIR + ap) * NCH + tid] = make_float2(f1, f2);
            float g1 = f1 * f1, g2 = f2 * f2;
            ull gp = pk2(g1 - g2, g1 + g2);    // (gd for even mi, gs for odd mi)
            u2[0] = fma2(gp, a01.x, u2[0]);
            u2[1] = fma2(gp, a01.y, u2[1]);
            u2[2] = fma2(gp, a23.x, u2[2]);
            u2[3] = fma2(gp, a23.y, u2[3]);
            u2[4] = fma2(gp, a45.x, u2[4]);
            u2[5] = fma2(gp, a45.y, u2[5]);
        }

        float us[11];
        upk2(u2[0], us[0], us[1]);  upk2(u2[1], us[2], us[3]);
        upk2(u2[2], us[4], us[5]);  upk2(u2[3], us[6], us[7]);
        upk2(u2[4], us[8], us[9]);
        { float junk; upk2(u2[5], us[10], junk); }
        #pragma unroll
        for (int k = 0; k < DIM; ++k)
            p1[k] = fmaf(sPw[b * DIM + k], us[KM[k]], p1[k]);
    }

    // ---- build packed p1 operands for pass B ----
    ull ppk[21];
    #pragma unroll
    for (int i = 0; i < 21; ++i)
        ppk[i] = pk2(KA[i] >= 0 ? p1[KA[i]] : 0.0f,
                     KB[i] >= 0 ? p1[KB[i]] : 0.0f);

    // ---- weights + fold nu=0/1 into acc (c0 reloaded; L2-resident) ----
    float w2[6], acc[DIM];
    {
        float w0[6], w1[6];
        #pragma unroll
        for (int l = 0; l < 6; ++l) { w0[l] = 0.f; w1[l] = 0.f; w2[l] = 0.f; }
        #pragma unroll 1
        for (int e = 0; e < NTYPE; ++e) {
            float a = sAt[e];
            const float* Wp = W + ((size_t)e * NCH + tid) * 6;
            #pragma unroll
            for (int l = 0; l < 6; ++l) {
                w0[l] = fmaf(a, Wp[l],                       w0[l]);
                w1[l] = fmaf(a, Wp[NTYPE * NCH * 6 + l],     w1[l]);
                w2[l] = fmaf(a, Wp[2 * NTYPE * NCH * 6 + l], w2[l]);
            }
        }
        const float4* fp = reinterpret_cast<const float4*>(feat + base);
        #pragma unroll
        for (int q = 0; q < 9; ++q) {
            float4 cv = fp[q];
            acc[4*q+0] = fmaf(w0[KL[4*q+0]], cv.x, w1[KL[4*q+0]] * p1[4*q+0]);
            acc[4*q+1] = fmaf(w0[KL[4*q+1]], cv.y, w1[KL[4*q+1]] * p1[4*q+1]);
            acc[4*q+2] = fmaf(w0[KL[4*q+2]], cv.z, w1[KL[4*q+2]] * p1[4*q+2]);
            acc[4*q+3] = fmaf(w0[KL[4*q+3]], cv.w, w1[KL[4*q+3]] * p1[4*q+3]);
        }
    }

    // ============ pass B: p2 = Yw^T ((Y p1) * fg) ============================
    float p2[DIM];
    #pragma unroll
    for (int k = 0; k < DIM; ++k) p2[k] = 0.f;

    #pragma unroll 1
    for (int b = 0; b < NBETA; ++b) {
        const ulonglong2* pr = reinterpret_cast<const ulonglong2*>(sm + OFF_PKP + b * 44);
        ull pk[22];
        #pragma unroll
        for (int i = 0; i < 11; ++i) { ulonglong2 v = pr[i]; pk[2*i] = v.x; pk[2*i+1] = v.y; }

        ull t2[6] = {0,0,0,0,0,0};
        #pragma unroll
        for (int i = 0; i < 21; ++i) t2[JT[i]] = fma2(pk[i], ppk[i], t2[JT[i]]);

        ull u2[6] = {0,0,0,0,0,0};
        #pragma unroll
        for (int ap = 0; ap < NAPAIR; ++ap) {
            ulonglong2 a01 = anr[ap*3+0], a23 = anr[ap*3+1], a45 = anr[ap*3+2];
            ull sA = fma2(t2[2], a23.x, fma2(t2[1], a01.y, fma2(t2[0], a01.x, 0ULL)));
            ull sB = fma2(t2[5], a45.y, fma2(t2[4], a45.x, fma2(t2[3], a23.y, 0ULL)));
            ull sfo_fe = add2(sA, sB);
            float fo, fe; upk2(sfo_fe, fo, fe);
            float2 fg = sFg[(b * NAPAIR + ap) * NCH + tid];
            float g1 = (fe + fo) * fg.x;
            float g2 = (fe - fo) * fg.y;
            ull gp = pk2(g1 - g2, g1 + g2);
            u2[0] = fma2(gp, a01.x, u2[0]);
            u2[1] = fma2(gp, a01.y, u2[1]);
            u2[2] = fma2(gp, a23.x, u2[2]);
            u2[3] = fma2(gp, a23.y, u2[3]);
            u2[4] = fma2(gp, a45.x, u2[4]);
            u2[5] = fma2(gp, a45.y, u2[5]);
        }

        float us[11];
        upk2(u2[0], us[0], us[1]);  upk2(u2[1], us[2], us[3]);
        upk2(u2[2], us[4], us[5]);  upk2(u2[3], us[6], us[7]);
        upk2(u2[4], us[8], us[9]);
        { float junk; upk2(u2[5], us[10], junk); }
        #pragma unroll
        for (int k = 0; k < DIM; ++k)
            p2[k] = fmaf(sPw[b * DIM + k], us[KM[k]], p2[k]);
    }

    // ---- final combine + vectorized store ----
    float* op = out + base;
    #pragma unroll
    for (int q = 0; q < 9; ++q) {
        float4 v;
        v.x = fmaf(w2[KL[4*q+0]], p2[4*q+0], acc[4*q+0]);
        v.y = fmaf(w2[KL[4*q+1]], p2[4*q+1], acc[4*q+1]);
        v.z = fmaf(w2[KL[4*q+2]], p2[4*q+2], acc[4*q+2]);
        v.w = fmaf(w2[KL[4*q+3]], p2[4*q+3], acc[4*q+3]);
        *reinterpret_cast<float4*>(op + 4 * q) = v;
    }
}

// ---------------------------------------------------------------------------
extern "C" void kernel_launch(void* const* d_in, const int* in_sizes, int n_in,
                              void* d_out, int out_size) {
    // Bind inputs BY SIZE: feat = largest (n*128*36), W = 23040, atype = n*10
    const float* feat  = nullptr;
    const float* atype = nullptr;
    const float* W     = nullptr;

    int fi = 0;
    for (int i = 1; i < n_in; ++i) if (in_sizes[i] > in_sizes[fi]) fi = i;
    feat = (const float*)d_in[fi];
    int n_atoms = in_sizes[fi] / (NCH * DIM);

    for (int i = 0; i < n_in; ++i) {
        if (i == fi) continue;
        if (in_sizes[i] == WSIZE && W == nullptr && in_sizes[i] != n_atoms * NTYPE) {
            W = (const float*)d_in[i];
        } else if (in_sizes[i] == n_atoms * NTYPE && atype == nullptr) {
            atype = (const float*)d_in[i];
        } else if (W == nullptr) {
            W = (const float*)d_in[i];
        } else {
            atype = (const float*)d_in[i];
        }
    }
    if (!atype) atype = (const float*)d_in[1];
    if (!W)     W     = (const float*)d_in[2];

    float* out = (float*)d_out;

    // smem: HDR floats header + 12*6*128 float2 fg = 4192 + 73728 = 77920 B
    size_t smem = (size_t)HDR * sizeof(float) +
                  (size_t)NBETA * NAPAIR * NCH * sizeof(float2);
    cudaFuncSetAttribute(tp_main_kernel,
                         cudaFuncAttributeMaxDynamicSharedMemorySize, (int)smem);

    init_tables_kernel<<<1, 32>>>();
    tp_main_kernel<<<n_atoms, NCH, smem>>>(feat, atype, W, out);
}

// round 10
// speedup vs baseline: 2.1385x; 1.0901x over previous
#include <cuda_runtime.h>
#include <cuda_fp16.h>
#include <math.h>

#ifndef M_PI
#define M_PI 3.14159265358979323846
#endif

#define NBETA   12
#define NAPAIR  6
#define NALPHA  12
#define DIM     36
#define NCH     128
#define NTYPE   10
#define WSIZE   (3 * NTYPE * NCH * 6)   // 23040

typedef unsigned long long ull;

// ---- packed f32x2 helpers (FFMA2 path; ptxas never emits these from C++) ----
__device__ __forceinline__ ull pk2(float lo, float hi) {
    ull r; asm("mov.b64 %0, {%1, %2};" : "=l"(r) : "f"(lo), "f"(hi)); return r;
}
__device__ __forceinline__ void upk2(ull v, float& lo, float& hi) {
    asm("mov.b64 {%0, %1}, %2;" : "=f"(lo), "=f"(hi) : "l"(v));
}
__device__ __forceinline__ ull fma2(ull a, ull b, ull c) {
    ull d; asm("fma.rn.f32x2 %0, %1, %2, %3;" : "=l"(d) : "l"(a), "l"(b), "l"(c)); return d;
}
__device__ __forceinline__ ull add2(ull a, ull b) {
    ull d; asm("add.rn.f32x2 %0, %1, %2;" : "=l"(d) : "l"(a), "l"(b)); return d;
}

// ---- 12-point Gauss-Legendre nodes/weights ----
__constant__ double c_glx[NBETA] = {
    -0.9815606342467192, -0.9041172563704749, -0.7699026741943047,
    -0.5873179542866175, -0.3678314989981802, -0.1252334085114689,
     0.1252334085114689,  0.3678314989981802,  0.5873179542866175,
     0.7699026741943047,  0.9041172563704749,  0.9815606342467192
};
__constant__ double c_glw[NBETA] = {
    0.0471753363865118, 0.1069393259953184, 0.1600783285433462,
    0.2031674267230659, 0.2334925365383548, 0.2491470458134028,
    0.2491470458134028, 0.2334925365383548, 0.2031674267230659,
    0.1600783285433462, 0.1069393259953184, 0.0471753363865118
};

// Pair table for the l<->m contractions: lane.lo -> k=PKA[i] (mi even = 2*PJT[i]),
// lane.hi -> k=PKB[i] (mi odd = 2*PJT[i]+1); -1 = zero lane. Covers all 36 k once.
__constant__ int PKA[21] = {25,-1, 9,17,27,-1, 1, 5,11,19,29,-1, 3, 7,13,21,31,15,23,33,35};
__constant__ int PKB[21] = {16,26, 4,10,18,28, 0, 2, 6,12,20,30, 8,14,22,32,-1,24,34,-1,-1};
__constant__ int PJT[21] = { 0, 0, 1, 1, 1, 1, 2, 2, 2, 2, 2, 2, 3, 3, 3, 3, 3, 4, 4, 4, 5};

// Device table layout (floats):
//   [0,432)     Pw  scalar  Pwk[b][k]
//   [432,960)   PKP packed  12 b x 22 entries x 2
//   [960,1032)  AN2 packed  6 ap x 6 packs x 2
#define OFF_PW   0
#define OFF_PKP  432
#define OFF_AN2  960
#define TBL_SIZE 1032
#define OFF_AT   1032
#define HDR      1048
__device__ float g_tbl[TBL_SIZE];

__global__ void init_tables_kernel() {
    int t = threadIdx.x;
    if (t < NBETA) {
        double x = c_glx[t];
        double w = c_glw[t];
        double P[6][6];
        double s = sqrt(fmax(1.0 - x * x, 0.0));
        P[0][0] = sqrt(1.0 / (4.0 * M_PI));
        for (int m = 1; m <= 5; ++m)
            P[m][m] = sqrt((2.0 * m + 1.0) / (2.0 * m)) * s * P[m - 1][m - 1];
        for (int m = 0; m < 5; ++m)
            P[m + 1][m] = sqrt(2.0 * m + 3.0) * x * P[m][m];
        for (int m = 0; m <= 5; ++m)
            for (int l = m + 2; l <= 5; ++l) {
                double aa = sqrt((4.0 * l * l - 1.0) / ((double)l * l - (double)m * m));
                double bb = sqrt((((l - 1.0) * (l - 1.0)) - (double)m * m) /
                                 (4.0 * (l - 1.0) * (l - 1.0) - 1.0));
                P[l][m] = aa * (x * P[l - 1][m] - bb * P[l - 2][m]);
            }
        double wfac = w * (2.0 * M_PI / (double)NALPHA);
        float Pk[DIM];
        for (int k = 0; k < DIM; ++k) {
            int l = 0;
            while (k >= (l + 1) * (l + 1)) ++l;
            int m = k - l * l - l;
            double v = P[l][m < 0 ? -m : m];
            Pk[k] = (float)v;
            g_tbl[OFF_PW + t * DIM + k] = (float)(v * wfac);
        }
        for (int i = 0; i < 21; ++i) {
            int kA = PKA[i], kB = PKB[i];
            g_tbl[OFF_PKP + t * 44 + 2 * i + 0] = (kA >= 0) ? Pk[kA] : 0.0f;
            g_tbl[OFF_PKP + t * 44 + 2 * i + 1] = (kB >= 0) ? Pk[kB] : 0.0f;
        }
        g_tbl[OFF_PKP + t * 44 + 42] = 0.0f;
        g_tbl[OFF_PKP + t * 44 + 43] = 0.0f;
    } else if (t < NBETA + NAPAIR) {
        int a = t - NBETA;
        double alpha = a * (2.0 * M_PI / (double)NALPHA);
        double s2 = sqrt(2.0);
        float ang[11];
        ang[5] = 1.0f;
        for (int m = 1; m <= 5; ++m) {
            ang[5 + m] = (float)(s2 * cos(m * alpha));
            ang[5 - m] = (float)(s2 * sin(m * alpha));
        }
        for (int j = 0; j < 5; ++j) {
            g_tbl[OFF_AN2 + a * 12 + 2 * j + 0] = ang[2 * j];
            g_tbl[OFF_AN2 + a * 12 + 2 * j + 1] = ang[2 * j + 1];
        }
        g_tbl[OFF_AN2 + a * 12 + 10] = ang[10];
        g_tbl[OFF_AN2 + a * 12 + 11] = 0.0f;
    }
}

// ---------------------------------------------------------------------------
// Main kernel: block = 1 atom, thread = 1 channel. FFMA2 hot loops +
// alpha-pair symmetry + fp16x2 fg cache; 3 blocks/SM (170-reg cap).
// ---------------------------------------------------------------------------
__global__ __launch_bounds__(NCH, 3) void tp_main_kernel(
    const float* __restrict__ feat,    // [n, 128, 36]
    const float* __restrict__ atype,   // [n, 10]
    const float* __restrict__ W,       // [3, 10, 128, 6]
    float* __restrict__ out)           // [n, 128, 36]
{
    constexpr int KA[21] = {25,-1, 9,17,27,-1, 1, 5,11,19,29,-1, 3, 7,13,21,31,15,23,33,35};
    constexpr int KB[21] = {16,26, 4,10,18,28, 0, 2, 6,12,20,30, 8,14,22,32,-1,24,34,-1,-1};
    constexpr int JT[21] = { 0, 0, 1, 1, 1, 1, 2, 2, 2, 2, 2, 2, 3, 3, 3, 3, 3, 4, 4, 4, 5};
    constexpr int KM[DIM] = {5,
                             4,5,6,
                             3,4,5,6,7,
                             2,3,4,5,6,7,8,
                             1,2,3,4,5,6,7,8,9,
                             0,1,2,3,4,5,6,7,8,9,10};
    constexpr int KL[DIM] = {0,
                             1,1,1,
                             2,2,2,2,2,
                             3,3,3,3,3,3,3,
                             4,4,4,4,4,4,4,4,4,
                             5,5,5,5,5,5,5,5,5,5,5};

    extern __shared__ float sm[];
    float*   sPw = sm + OFF_PW;
    float*   sAt = sm + OFF_AT;
    __half2* sFg = reinterpret_cast<__half2*>(sm + HDR);   // [b*6+ap][tid]

    const int tid = threadIdx.x;
    const int n   = blockIdx.x;

    for (int i = tid; i < TBL_SIZE; i += NCH) sm[i] = g_tbl[i];
    if (tid < NTYPE) sAt[tid] = atype[(size_t)n * NTYPE + tid];
    __syncthreads();

    const size_t base = ((size_t)n * NCH + tid) * DIM;

    // ---- load coefficients and build packed operand set for pass A ----
    ull cpk[21];
    {
        float c0[DIM];
        const float4* fp = reinterpret_cast<const float4*>(feat + base);
        #pragma unroll
        for (int q = 0; q < 9; ++q) {
            float4 v = fp[q];
            c0[4*q+0] = v.x; c0[4*q+1] = v.y; c0[4*q+2] = v.z; c0[4*q+3] = v.w;
        }
        #pragma unroll
        for (int i = 0; i < 21; ++i)
            cpk[i] = pk2(KA[i] >= 0 ? c0[KA[i]] : 0.0f,
                         KB[i] >= 0 ? c0[KB[i]] : 0.0f);
    }

    const ulonglong2* anr = reinterpret_cast<const ulonglong2*>(sm + OFF_AN2);

    // =================== pass A: fg = Y c0 ; p1 = Yw^T (fg*fg) ===============
    float p1[DIM];
    #pragma unroll
    for (int k = 0; k < DIM; ++k) p1[k] = 0.f;

    #pragma unroll 1
    for (int b = 0; b < NBETA; ++b) {
        const ulonglong2* pr = reinterpret_cast<const ulonglong2*>(sm + OFF_PKP + b * 44);
        ull pk[22];
        #pragma unroll
        for (int i = 0; i < 11; ++i) { ulonglong2 v = pr[i]; pk[2*i] = v.x; pk[2*i+1] = v.y; }

        ull t2[6] = {0,0,0,0,0,0};
        #pragma unroll
        for (int i = 0; i < 21; ++i) t2[JT[i]] = fma2(pk[i], cpk[i], t2[JT[i]]);

        ull u2[6] = {0,0,0,0,0,0};
        #pragma unroll
        for (int ap = 0; ap < NAPAIR; ++ap) {
            ulonglong2 a01 = anr[ap*3+0], a23 = anr[ap*3+1], a45 = anr[ap*3+2];
            ull sA = fma2(t2[2], a23.x, fma2(t2[1], a01.y, fma2(t2[0], a01.x, 0ULL)));
            ull sB = fma2(t2[5], a45.y, fma2(t2[4], a45.x, fma2(t2[3], a23.y, 0ULL)));
            ull sfo_fe = add2(sA, sB);
            float fo, fe; upk2(sfo_fe, fo, fe);
            float f1 = fe + fo, f2 = fe - fo;
            sFg[(b * NAPAIR + ap) * NCH + tid] = __floats2half2_rn(f1, f2);
            float g1 = f1 * f1, g2 = f2 * f2;     // exact f in pass A
            ull gp = pk2(g1 - g2, g1 + g2);       // (gd even-mi, gs odd-mi)
            u2[0] = fma2(gp, a01.x, u2[0]);
            u2[1] = fma2(gp, a01.y, u2[1]);
            u2[2] = fma2(gp, a23.x, u2[2]);
            u2[3] = fma2(gp, a23.y, u2[3]);
            u2[4] = fma2(gp, a45.x, u2[4]);
            u2[5] = fma2(gp, a45.y, u2[5]);
        }

        float us[11];
        upk2(u2[0], us[0], us[1]);  upk2(u2[1], us[2], us[3]);
        upk2(u2[2], us[4], us[5]);  upk2(u2[3], us[6], us[7]);
        upk2(u2[4], us[8], us[9]);
        { float junk; upk2(u2[5], us[10], junk); }
        #pragma unroll
        for (int k = 0; k < DIM; ++k)
            p1[k] = fmaf(sPw[b * DIM + k], us[KM[k]], p1[k]);
    }

    // ---- build packed p1 operands for pass B ----
    ull ppk[21];
    #pragma unroll
    for (int i = 0; i < 21; ++i)
        ppk[i] = pk2(KA[i] >= 0 ? p1[KA[i]] : 0.0f,
                     KB[i] >= 0 ? p1[KB[i]] : 0.0f);

    // ---- weights + fold nu=0/1 into acc (c0 reloaded; L2-resident) ----
    float w2[6], acc[DIM];
    {
        float w0[6], w1[6];
        #pragma unroll
        for (int l = 0; l < 6; ++l) { w0[l] = 0.f; w1[l] = 0.f; w2[l] = 0.f; }
        #pragma unroll 1
        for (int e = 0; e < NTYPE; ++e) {
            float a = sAt[e];
            const float* Wp = W + ((size_t)e * NCH + tid) * 6;
            #pragma unroll
            for (int l = 0; l < 6; ++l) {
                w0[l] = fmaf(a, Wp[l],                       w0[l]);
                w1[l] = fmaf(a, Wp[NTYPE * NCH * 6 + l],     w1[l]);
                w2[l] = fmaf(a, Wp[2 * NTYPE * NCH * 6 + l], w2[l]);
            }
        }
        const float4* fp = reinterpret_cast<const float4*>(feat + base);
        #pragma unroll
        for (int q = 0; q < 9; ++q) {
            float4 cv = fp[q];
            acc[4*q+0] = fmaf(w0[KL[4*q+0]], cv.x, w1[KL[4*q+0]] * p1[4*q+0]);
            acc[4*q+1] = fmaf(w0[KL[4*q+1]], cv.y, w1[KL[4*q+1]] * p1[4*q+1]);
            acc[4*q+2] = fmaf(w0[KL[4*q+2]], cv.z, w1[KL[4*q+2]] * p1[4*q+2]);
            acc[4*q+3] = fmaf(w0[KL[4*q+3]], cv.w, w1[KL[4*q+3]] * p1[4*q+3]);
        }
    }

    // ============ pass B: p2 = Yw^T ((Y p1) * fg) ============================
    float p2[DIM];
    #pragma unroll
    for (int k = 0; k < DIM; ++k) p2[k] = 0.f;

    #pragma unroll 1
    for (int b = 0; b < NBETA; ++b) {
        const ulonglong2* pr = reinterpret_cast<const ulonglong2*>(sm + OFF_PKP + b * 44);
        ull pk[22];
        #pragma unroll
        for (int i = 0; i < 11; ++i) { ulonglong2 v = pr[i]; pk[2*i] = v.x; pk[2*i+1] = v.y; }

        ull t2[6] = {0,0,0,0,0,0};
        #pragma unroll
        for (int i = 0; i < 21; ++i) t2[JT[i]] = fma2(pk[i], ppk[i], t2[JT[i]]);

        ull u2[6] = {0,0,0,0,0,0};
        #pragma unroll
        for (int ap = 0; ap < NAPAIR; ++ap) {
            ulonglong2 a01 = anr[ap*3+0], a23 = anr[ap*3+1], a45 = anr[ap*3+2];
            ull sA = fma2(t2[2], a23.x, fma2(t2[1], a01.y, fma2(t2[0], a01.x, 0ULL)));
            ull sB = fma2(t2[5], a45.y, fma2(t2[4], a45.x, fma2(t2[3], a23.y, 0ULL)));
            ull sfo_fe = add2(sA, sB);
            float fo, fe; upk2(sfo_fe, fo, fe);
            float2 fg = __half22float2(sFg[(b * NAPAIR + ap) * NCH + tid]);
            float g1 = (fe + fo) * fg.x;
            float g2 = (fe - fo) * fg.y;
            ull gp = pk2(g1 - g2, g1 + g2);
            u2[0] = fma2(gp, a01.x, u2[0]);
            u2[1] = fma2(gp, a01.y, u2[1]);
            u2[2] = fma2(gp, a23.x, u2[2]);
            u2[3] = fma2(gp, a23.y, u2[3]);
            u2[4] = fma2(gp, a45.x, u2[4]);
            u2[5] = fma2(gp, a45.y, u2[5]);
        }

        float us[11];
        upk2(u2[0], us[0], us[1]);  upk2(u2[1], us[2], us[3]);
        upk2(u2[2], us[4], us[5]);  upk2(u2[3], us[6], us[7]);
        upk2(u2[4], us[8], us[9]);
        { float junk; upk2(u2[5], us[10], junk); }
        #pragma unroll
        for (int k = 0; k < DIM; ++k)
            p2[k] = fmaf(sPw[b * DIM + k], us[KM[k]], p2[k]);
    }

    // ---- final combine + vectorized store ----
    float* op = out + base;
    #pragma unroll
    for (int q = 0; q < 9; ++q) {
        float4 v;
        v.x = fmaf(w2[KL[4*q+0]], p2[4*q+0], acc[4*q+0]);
        v.y = fmaf(w2[KL[4*q+1]], p2[4*q+1], acc[4*q+1]);
        v.z = fmaf(w2[KL[4*q+2]], p2[4*q+2], acc[4*q+2]);
        v.w = fmaf(w2[KL[4*q+3]], p2[4*q+3], acc[4*q+3]);
        *reinterpret_cast<float4*>(op + 4 * q) = v;
    }
}

// ---------------------------------------------------------------------------
extern "C" void kernel_launch(void* const* d_in, const int* in_sizes, int n_in,
                              void* d_out, int out_size) {
    // Bind inputs BY SIZE: feat = largest (n*128*36), W = 23040, atype = n*10
    const float* feat  = nullptr;
    const float* atype = nullptr;
    const float* W     = nullptr;

    int fi = 0;
    for (int i = 1; i < n_in; ++i) if (in_sizes[i] > in_sizes[fi]) fi = i;
    feat = (const float*)d_in[fi];
    int n_atoms = in_sizes[fi] / (NCH * DIM);

    for (int i = 0; i < n_in; ++i) {
        if (i == fi) continue;
        if (in_sizes[i] == WSIZE && W == nullptr && in_sizes[i] != n_atoms * NTYPE) {
            W = (const float*)d_in[i];
        } else if (in_sizes[i] == n_atoms * NTYPE && atype == nullptr) {
            atype = (const float*)d_in[i];
        } else if (W == nullptr) {
            W = (const float*)d_in[i];
        } else {
            atype = (const float*)d_in[i];
        }
    }
    if (!atype) atype = (const float*)d_in[1];
    if (!W)     W     = (const float*)d_in[2];

    float* out = (float*)d_out;

    // smem: HDR floats + 12*6*128 half2 fg = 4192 + 36864 = 41056 B
    size_t smem = (size_t)HDR * sizeof(float) +
                  (size_t)NBETA * NAPAIR * NCH * sizeof(__half2);
    cudaFuncSetAttribute(tp_main_kernel,
                         cudaFuncAttributeMaxDynamicSharedMemorySize, (int)smem);

    init_tables_kernel<<<1, 32>>>();
    tp_main_kernel<<<n_atoms, NCH, smem>>>(feat, atype, W, out);
}